// round 12
// baseline (speedup 1.0000x reference)
#include <cuda_runtime.h>
#include <cuda_bf16.h>
#include <math.h>
#include <stdint.h>

#define H 4
#define Bb 8
#define Nn 1024
#define INF_ 1024
#define E 256
#define A_ 64
#define BN_ROWS 8192        /* B*N */
#define ALPHA 0.2f
#define P2 132              /* smem row pitch in uint2 (1056B: +8 banks/row) */
#define ROWB 1056           /* P2 * 8 bytes */
#define STAGE_B 16896       /* 16 rows * 1056B */

// ---- scratch (static device memory; no runtime allocation) ----
__device__ float g_Wh[H * BN_ROWS * E];                  // 32 MB fp32 (compute_f)
__device__ uint2 g_xT[(INF_ / 2) * BN_ROWS];             // 32 MB  [k2][m] hi/lo bf16 pairs
__device__ uint2 g_WT[H * (INF_ / 2) * E];               // 4 MB   [h][k2][n]
__device__ uint2 g_WhT[(H * BN_ROWS / 2) * E];           // 32 MB  [word][e], word pairs rows (r, r+8) per 16-group
__device__ float g_f1[H * BN_ROWS];
__device__ float g_E1[H * BN_ROWS];
__device__ float g_F1[H * BN_ROWS];
__device__ float4 g_pack[H * BN_ROWS];                   // (f2, exp(f2), exp(.2 f2), 0)
__device__ unsigned g_adjbits[Bb * Nn * (Nn / 32)];      // 1 MB packed adjacency
__device__ float g_feat[(size_t)BN_ROWS * H * E];        // 32 MB [row][h*E+e]

// ---- helpers ----
__device__ __forceinline__ uint32_t smem_u32(const void* p) {
    uint32_t a;
    asm("{ .reg .u64 t; cvta.to.shared.u64 t, %1; cvt.u32.u64 %0, t; }" : "=r"(a) : "l"(p));
    return a;
}
__device__ __forceinline__ uint32_t bfpack(float lo, float hi) {
    uint32_t r;
    asm("cvt.rn.bf16x2.f32 %0, %1, %2;" : "=r"(r) : "f"(hi), "f"(lo));
    return r;
}
__device__ __forceinline__ float bfres(float v) {
    return v - __bfloat162float(__float2bfloat16(v));
}
__device__ __forceinline__ uint2 split2(float a, float b) {
    uint2 r;
    r.x = bfpack(a, b);
    r.y = bfpack(bfres(a), bfres(b));
    return r;
}
__device__ __forceinline__ void cpa16(uint32_t dst, const void* src) {
    asm volatile("cp.async.cg.shared.global [%0], [%1], 16;" :: "r"(dst), "l"(src));
}
#define CP_COMMIT() asm volatile("cp.async.commit_group;" ::: "memory")
#define CP_WAIT(N)  asm volatile("cp.async.wait_group %0;" :: "n"(N) : "memory")

__device__ __forceinline__ void mma16(float c[4], const uint32_t a[4], const uint32_t b[2]) {
    asm volatile(
        "mma.sync.aligned.m16n8k16.row.col.f32.bf16.bf16.f32 "
        "{%0,%1,%2,%3}, {%4,%5,%6,%7}, {%8,%9}, {%0,%1,%2,%3};"
        : "+f"(c[0]), "+f"(c[1]), "+f"(c[2]), "+f"(c[3])
        : "r"(a[0]), "r"(a[1]), "r"(a[2]), "r"(a[3]), "r"(b[0]), "r"(b[1]));
}

// one k16 step over 128x128: frags are uint2 (hi,lo) -> 24 LDS.64, 48 MMA
__device__ __forceinline__ void k16_step2(const uint2 (*A)[P2], const uint2 (*B)[P2],
                                          int k2, int mw, int nw, int lq, int lr,
                                          float acc[4][4][4]) {
    uint2 a[4][4], b[4][2];
#pragma unroll
    for (int mt = 0; mt < 4; mt++) {
        int m0 = mw + 16 * mt + lr;
        a[mt][0] = A[k2 + lq][m0];
        a[mt][1] = A[k2 + lq][m0 + 8];
        a[mt][2] = A[k2 + lq + 4][m0];
        a[mt][3] = A[k2 + lq + 4][m0 + 8];
    }
#pragma unroll
    for (int nt = 0; nt < 4; nt++) {
        int n0 = nw + 8 * nt + lr;
        b[nt][0] = B[k2 + lq][n0];
        b[nt][1] = B[k2 + lq + 4][n0];
    }
#pragma unroll
    for (int mt = 0; mt < 4; mt++) {
        uint32_t ah[4] = {a[mt][0].x, a[mt][1].x, a[mt][2].x, a[mt][3].x};
#pragma unroll
        for (int nt = 0; nt < 4; nt++) {
            uint32_t bh[2] = {b[nt][0].x, b[nt][1].x};
            mma16(acc[mt][nt], ah, bh);
        }
    }
#pragma unroll
    for (int mt = 0; mt < 4; mt++) {
        uint32_t ah[4] = {a[mt][0].x, a[mt][1].x, a[mt][2].x, a[mt][3].x};
#pragma unroll
        for (int nt = 0; nt < 4; nt++) {
            uint32_t bl[2] = {b[nt][0].y, b[nt][1].y};
            mma16(acc[mt][nt], ah, bl);
        }
    }
#pragma unroll
    for (int mt = 0; mt < 4; mt++) {
        uint32_t al[4] = {a[mt][0].y, a[mt][1].y, a[mt][2].y, a[mt][3].y};
#pragma unroll
        for (int nt = 0; nt < 4; nt++) {
            uint32_t bh[2] = {b[nt][0].x, b[nt][1].x};
            mma16(acc[mt][nt], al, bh);
        }
    }
}

#define GEMM_SMEM (6 * STAGE_B)                 /* 3 stages A + 3 stages B */
#define ATT_SMEM  (6 * STAGE_B + 1024)

// ============================================================
// K0: pack adjacency int32 -> bitmask
// ============================================================
__global__ void pack_adj(const int* __restrict__ adj) {
    int idx = blockIdx.x * blockDim.x + threadIdx.x;
    unsigned m = __ballot_sync(0xffffffffu, adj[idx] > 0);
    if ((idx & 31) == 0) g_adjbits[idx >> 5] = m;
}

// ============================================================
// K0b: split+transpose x (8192x1024 f32) -> g_xT [512][8192] uint2
// ============================================================
__global__ void split_x(const float* __restrict__ x) {
    __shared__ uint2 ts[32][33];
    int m0 = blockIdx.x * 32, k20 = blockIdx.y * 32;
    int tx = threadIdx.x, ty = threadIdx.y;
    for (int r = ty; r < 32; r += 8) {
        float2 w = *(const float2*)(x + (size_t)(m0 + r) * INF_ + 2 * (k20 + tx));
        ts[tx][r] = split2(w.x, w.y);
    }
    __syncthreads();
    for (int r = ty; r < 32; r += 8)
        g_xT[(size_t)(k20 + r) * BN_ROWS + m0 + tx] = ts[r][tx];
}

// ============================================================
// K0c: split W (H,1024,256) -> g_WT [h][512][256] uint2 (adjacent k rows)
// ============================================================
__global__ void split_W(const float* __restrict__ W) {
    int idx = blockIdx.x * blockDim.x + threadIdx.x;    // H*512*64
    int p = idx >> 6;                                    // h*512 + k2
    int n4 = (idx & 63) * 4;
    const float* r0 = W + (size_t)(2 * p) * E + n4;
    const float* r1 = r0 + E;
    float4 u = *(const float4*)r0;
    float4 v = *(const float4*)r1;
    uint2* o = g_WT + (size_t)p * E + n4;
    o[0] = split2(u.x, v.x);
    o[1] = split2(u.y, v.y);
    o[2] = split2(u.z, v.z);
    o[3] = split2(u.w, v.w);
}

// ============================================================
// K1: Wh = x @ W[h], bf16x3 mma, 3-stage cp.async pipeline.
// Epilogue: fp32 store + fused split into g_WhT ((r, r+8) pairing).
// grid (E/128=2, BN/128=64, H=4), 256 thr.
// ============================================================
__global__ void __launch_bounds__(256, 2) wh_gemm_mma() {
    extern __shared__ uint2 smw2[];
    uint32_t sb = smem_u32(smw2);
    const uint2 (*Abuf)[P2] = (const uint2 (*)[P2])smw2;            // 3 stages x 16 rows
    const uint2 (*Bbuf)[P2] = (const uint2 (*)[P2])(smw2 + 48 * P2);
    int h = blockIdx.z;
    int rowBase = blockIdx.y * 128;
    int colBase = blockIdx.x * 128;
    int tid = threadIdx.x, lane = tid & 31, wid = tid >> 5;
    int lq = lane & 3, lr = lane >> 2;
    int mw = (wid & 1) * 64, nw = (wid >> 1) * 32;

    // per-thread loader bases (rows r0+4i, 16B chunk q)
    int r0 = tid >> 6, q = tid & 63;
    uint32_t sA = sb + r0 * ROWB + q * 16;
    uint32_t sB = sA + 3 * STAGE_B;
    const char* gA = (const char*)(g_xT + rowBase) + (size_t)r0 * 65536 + q * 16;
    const char* gB = (const char*)(g_WT + (size_t)h * 512 * E + colBase) + r0 * 2048 + q * 16;

#define WH_LD(S, RO)                                                           \
    do {                                                                       \
        cpa16(sA + (S) * STAGE_B + 0 * 4 * ROWB, gA + (size_t)((RO) + 0) * 65536);  \
        cpa16(sA + (S) * STAGE_B + 1 * 4 * ROWB, gA + (size_t)((RO) + 4) * 65536);  \
        cpa16(sA + (S) * STAGE_B + 2 * 4 * ROWB, gA + (size_t)((RO) + 8) * 65536);  \
        cpa16(sA + (S) * STAGE_B + 3 * 4 * ROWB, gA + (size_t)((RO) + 12) * 65536); \
        cpa16(sB + (S) * STAGE_B + 0 * 4 * ROWB, gB + ((RO) + 0) * 2048);      \
        cpa16(sB + (S) * STAGE_B + 1 * 4 * ROWB, gB + ((RO) + 4) * 2048);      \
        cpa16(sB + (S) * STAGE_B + 2 * 4 * ROWB, gB + ((RO) + 8) * 2048);      \
        cpa16(sB + (S) * STAGE_B + 3 * 4 * ROWB, gB + ((RO) + 12) * 2048);     \
        CP_COMMIT();                                                           \
    } while (0)

#define WH_ITER(CUR, NXT, WGRP, DO)                                            \
    do {                                                                       \
        CP_WAIT(WGRP);                                                         \
        __syncthreads();                                                       \
        if (DO) WH_LD(NXT, 32);                                                \
        k16_step2(Abuf + (CUR) * 16, Bbuf + (CUR) * 16, 0, mw, nw, lq, lr, acc); \
        k16_step2(Abuf + (CUR) * 16, Bbuf + (CUR) * 16, 8, mw, nw, lq, lr, acc); \
        if (DO) { gA += 16 * 65536; gB += 16 * 2048; }                         \
    } while (0)

    WH_LD(0, 0);
    WH_LD(1, 16);

    float acc[4][4][4] = {};
    for (int c2 = 0; c2 < 10; c2++) {
        WH_ITER(0, 2, 1, true);
        WH_ITER(1, 0, 1, true);
        WH_ITER(2, 1, 1, true);
    }
    WH_ITER(0, 2, 1, false);
    WH_ITER(1, 0, 0, false);
#undef WH_ITER
#undef WH_LD

    float* Cp = g_Wh + (size_t)h * BN_ROWS * E;
#pragma unroll
    for (int mt = 0; mt < 4; mt++) {
        int r = rowBase + mw + 16 * mt + lr;
        size_t wword = ((size_t)h * BN_ROWS + rowBase + mw + 16 * mt) / 2 + lr;
#pragma unroll
        for (int nt = 0; nt < 4; nt++) {
            int cc = colBase + nw + 8 * nt + 2 * lq;
            *(float2*)(Cp + (size_t)r * E + cc) =
                make_float2(acc[mt][nt][0], acc[mt][nt][1]);
            *(float2*)(Cp + (size_t)(r + 8) * E + cc) =
                make_float2(acc[mt][nt][2], acc[mt][nt][3]);
            g_WhT[wword * E + cc]     = split2(acc[mt][nt][0], acc[mt][nt][2]);
            g_WhT[wword * E + cc + 1] = split2(acc[mt][nt][1], acc[mt][nt][3]);
        }
    }
}

// ============================================================
// K2: f1/f2 = Wh . a1/a2 + factored exps. Warp per row.
// ============================================================
__global__ void compute_f(const float* __restrict__ a1, const float* __restrict__ a2) {
    int r = (blockIdx.x * blockDim.x + threadIdx.x) >> 5;
    int lane = threadIdx.x & 31;
    int h = r >> 13;
    const float* wh = g_Wh + (size_t)r * E;
    const float* a1p = a1 + h * E;
    const float* a2p = a2 + h * E;
    float s1 = 0.f, s2 = 0.f;
#pragma unroll
    for (int i = 0; i < 8; i++) {
        int e = lane + i * 32;
        float v = wh[e];
        s1 += v * a1p[e];
        s2 += v * a2p[e];
    }
#pragma unroll
    for (int o = 16; o > 0; o >>= 1) {
        s1 += __shfl_xor_sync(0xffffffffu, s1, o);
        s2 += __shfl_xor_sync(0xffffffffu, s2, o);
    }
    if (lane == 0) {
        g_f1[r] = s1;
        g_E1[r] = __expf(s1);
        g_F1[r] = __expf(ALPHA * s1);
        g_pack[r] = make_float4(s2, __expf(s2), __expf(ALPHA * s2), 0.f);
    }
}

// ============================================================
// K3: h' = att @ Wh_b, bf16x3 mma, 3-stage pipeline; A generated on the
// fly with the (j, j+8) 16-group pairing; B via cp.async from g_WhT.
// grid (E/128=2, Nn/128=8, H*Bb=32), 256 thr.
// ============================================================
__global__ void __launch_bounds__(256, 2) att_gemm_mma() {
    extern __shared__ uint2 smw2[];
    uint32_t sb = smem_u32(smw2);
    uint2 (*Abuf)[P2] = (uint2 (*)[P2])smw2;                        // 3 stages
    const uint2 (*Bbuf)[P2] = (const uint2 (*)[P2])(smw2 + 48 * P2);
    float* Ssum = (float*)(smw2 + 96 * P2);       // [2][128]
    int hb = blockIdx.z;
    int h = hb >> 3, b = hb & 7;
    int rowBase = blockIdx.y * 128;
    int colBase = blockIdx.x * 128;
    int base = h * BN_ROWS + b * Nn;
    int tid = threadIdx.x, lane = tid & 31, wid = tid >> 5;
    int lq = lane & 3, lr = lane >> 2;
    int mw = (wid & 1) * 64, nw = (wid >> 1) * 32;

    int ig = tid & 127;
    int jp = tid >> 7;
    int gi = base + rowBase + ig;
    float f1v = g_f1[gi], E1v = g_E1[gi], F1v = g_F1[gi];
    const unsigned* awp = g_adjbits + (size_t)(b * Nn + rowBase + ig) * (Nn / 32);
    float rsum = 0.f;

    // B loader bases
    int r0 = tid >> 6, q = tid & 63;
    uint32_t sB = sb + 3 * STAGE_B + r0 * ROWB + q * 16;
    const char* gB = (const char*)(g_WhT + (size_t)((h * BN_ROWS + b * Nn) >> 1) * E + colBase)
                     + r0 * 2048 + q * 16;

#define ATT_LD(S, RO)                                                          \
    do {                                                                       \
        cpa16(sB + (S) * STAGE_B + 0 * 4 * ROWB, gB + ((RO) + 0) * 2048);      \
        cpa16(sB + (S) * STAGE_B + 1 * 4 * ROWB, gB + ((RO) + 4) * 2048);      \
        cpa16(sB + (S) * STAGE_B + 2 * 4 * ROWB, gB + ((RO) + 8) * 2048);      \
        cpa16(sB + (S) * STAGE_B + 3 * 4 * ROWB, gB + ((RO) + 12) * 2048);     \
        CP_COMMIT();                                                           \
    } while (0)

// word w = 8*jp + t packs js (K0 + 16*jp + t) and (K0 + 16*jp + t + 8)
#define GENA(S, K0)                                                            \
    do {                                                                       \
        unsigned wb = awp[(K0) >> 5] >> (16 * jp);                             \
        _Pragma("unroll")                                                      \
        for (int t = 0; t < 8; t++) {                                          \
            int j = (K0) + 16 * jp + t;                                        \
            float4 p0 = g_pack[base + j];                                      \
            float4 p1 = g_pack[base + j + 8];                                  \
            float s0 = f1v + p0.x;                                             \
            float v0 = ((wb >> t) & 1u)                                        \
                           ? ((s0 > 0.f) ? E1v * p0.y : F1v * p0.z) : 0.f;     \
            float s1 = f1v + p1.x;                                             \
            float v1 = ((wb >> (t + 8)) & 1u)                                  \
                           ? ((s1 > 0.f) ? E1v * p1.y : F1v * p1.z) : 0.f;     \
            rsum += v0 + v1;                                                   \
            Abuf[(S) * 16 + 8 * jp + t][ig] = split2(v0, v1);                  \
        }                                                                      \
    } while (0)

#define ATT_ITER(CUR, NXT, WGRP, DO)                                           \
    do {                                                                       \
        CP_WAIT(WGRP);                                                         \
        __syncthreads();                                                       \
        if (DO) ATT_LD(NXT, 32);                                               \
        k16_step2((const uint2 (*)[P2])(Abuf + (CUR) * 16), Bbuf + (CUR) * 16, \
                  0, mw, nw, lq, lr, acc);                                     \
        if (DO) GENA(NXT, jb + 64);                                            \
        k16_step2((const uint2 (*)[P2])(Abuf + (CUR) * 16), Bbuf + (CUR) * 16, \
                  8, mw, nw, lq, lr, acc);                                     \
        if (DO) { gB += 16 * 2048; jb += 32; }                                 \
    } while (0)

    // prologue: generate A stages 0,1; commit B stages 0,1
    GENA(0, 0);
    GENA(1, 32);
    ATT_LD(0, 0);
    ATT_LD(1, 16);
    int jb = 0;

    float acc[4][4][4] = {};
    for (int c2 = 0; c2 < 10; c2++) {
        ATT_ITER(0, 2, 1, true);
        ATT_ITER(1, 0, 1, true);
        ATT_ITER(2, 1, 1, true);
    }
    ATT_ITER(0, 2, 1, false);
    ATT_ITER(1, 0, 0, false);
#undef ATT_ITER
#undef GENA
#undef ATT_LD

    Ssum[jp * 128 + ig] = rsum;
    __syncthreads();

#pragma unroll
    for (int mt = 0; mt < 4; mt++) {
        int rl = mw + 16 * mt + lr;
        float S0 = Ssum[rl] + Ssum[128 + rl];
        float S8 = Ssum[rl + 8] + Ssum[128 + rl + 8];
        float sc0 = (S0 > 0.f) ? (1.0f / S0) : 0.f;
        float sc8 = (S8 > 0.f) ? (1.0f / S8) : 0.f;
        float* f0 = g_feat + (size_t)(b * Nn + rowBase + rl) * (H * E) + h * E + colBase;
        float* f8 = g_feat + (size_t)(b * Nn + rowBase + rl + 8) * (H * E) + h * E + colBase;
#pragma unroll
        for (int nt = 0; nt < 4; nt++) {
            int cc = nw + 8 * nt + 2 * lq;
            float v0 = acc[mt][nt][0] * sc0;
            float v1 = acc[mt][nt][1] * sc0;
            float v2 = acc[mt][nt][2] * sc8;
            float v3 = acc[mt][nt][3] * sc8;
            v0 = (v0 > 0.f) ? v0 : expm1f(v0);
            v1 = (v1 > 0.f) ? v1 : expm1f(v1);
            v2 = (v2 > 0.f) ? v2 : expm1f(v2);
            v3 = (v3 > 0.f) ? v3 : expm1f(v3);
            *(float2*)(f0 + cc) = make_float2(v0, v1);
            *(float2*)(f8 + cc) = make_float2(v2, v3);
        }
    }
}

// ============================================================
// K5: out (8192x64) = feat (8192x1024) @ W_act (1024x64) + b_act
// ============================================================
__global__ void __launch_bounds__(256) final_gemm(const float* __restrict__ W_act,
                                                  const float* __restrict__ b_act,
                                                  float* __restrict__ out) {
    __shared__ float As[16][34];
    __shared__ float Bs[16][68];
    int rowBase = blockIdx.y * 32;
    int tid = threadIdx.x;
    int tx = tid & 15, ty = tid >> 4;
    float acc[2][4] = {};
    for (int k0 = 0; k0 < H * E; k0 += 16) {
        if (tid < 128) {
            int r = tid >> 2, ch = tid & 3;
            float4 v = *(const float4*)(g_feat + (size_t)(rowBase + r) * (H * E) + k0 + 4 * ch);
            As[4 * ch + 0][r] = v.x; As[4 * ch + 1][r] = v.y;
            As[4 * ch + 2][r] = v.z; As[4 * ch + 3][r] = v.w;
        }
        {
            int r = tid >> 4, ch = tid & 15;
            float4 v = *(const float4*)(W_act + (size_t)(k0 + r) * A_ + 4 * ch);
            *(float4*)&Bs[r][4 * ch] = v;
        }
        __syncthreads();
#pragma unroll
        for (int kk = 0; kk < 16; kk++) {
            float a0 = As[kk][ty * 2], a1v = As[kk][ty * 2 + 1];
            float4 bv = *(float4*)&Bs[kk][tx * 4];
            acc[0][0] += a0 * bv.x; acc[0][1] += a0 * bv.y;
            acc[0][2] += a0 * bv.z; acc[0][3] += a0 * bv.w;
            acc[1][0] += a1v * bv.x; acc[1][1] += a1v * bv.y;
            acc[1][2] += a1v * bv.z; acc[1][3] += a1v * bv.w;
        }
        __syncthreads();
    }
    float4 bias = *(const float4*)(b_act + tx * 4);
#pragma unroll
    for (int i = 0; i < 2; i++) {
        int r = rowBase + ty * 2 + i;
        float4 v = make_float4(acc[i][0] + bias.x, acc[i][1] + bias.y,
                               acc[i][2] + bias.z, acc[i][3] + bias.w);
        *(float4*)(out + (size_t)r * A_ + tx * 4) = v;
    }
}

extern "C" void kernel_launch(void* const* d_in, const int* in_sizes, int n_in,
                              void* d_out, int out_size) {
    const float* x     = (const float*)d_in[0];
    const int*   adj   = (const int*)d_in[1];
    const float* W     = (const float*)d_in[2];
    const float* a1    = (const float*)d_in[3];
    const float* a2    = (const float*)d_in[4];
    const float* W_act = (const float*)d_in[5];
    const float* b_act = (const float*)d_in[6];
    float* out = (float*)d_out;

    cudaFuncSetAttribute(wh_gemm_mma, cudaFuncAttributeMaxDynamicSharedMemorySize, GEMM_SMEM);
    cudaFuncSetAttribute(att_gemm_mma, cudaFuncAttributeMaxDynamicSharedMemorySize, ATT_SMEM);

    pack_adj<<<(Bb * Nn * Nn) / 256, 256>>>(adj);
    split_x<<<dim3(BN_ROWS / 32, (INF_ / 2) / 32), dim3(32, 8)>>>(x);
    split_W<<<(H * (INF_ / 2) * (E / 4)) / 256, 256>>>(W);
    wh_gemm_mma<<<dim3(E / 128, BN_ROWS / 128, H), 256, GEMM_SMEM>>>();
    compute_f<<<(H * BN_ROWS) / 8, 256>>>(a1, a2);
    att_gemm_mma<<<dim3(E / 128, Nn / 128, H * Bb), 256, ATT_SMEM>>>();
    final_gemm<<<dim3(1, BN_ROWS / 32), 256>>>(W_act, b_act, out);
}

// round 13
// speedup vs baseline: 1.5836x; 1.5836x over previous
#include <cuda_runtime.h>
#include <cuda_bf16.h>
#include <math.h>
#include <stdint.h>

#define H 4
#define Bb 8
#define Nn 1024
#define INF_ 1024
#define E 256
#define A_ 64
#define BN_ROWS 8192        /* B*N */
#define ALPHA 0.2f
#define P2 132              /* smem row pitch in uint2 (1056B: +8 banks/row) */
#define ROWB 1056           /* P2 * 8 bytes */
#define STAGE_B 16896       /* 16 rows * 1056B */

// ---- scratch (static device memory; no runtime allocation) ----
__device__ uint2 g_xT[(INF_ / 2) * BN_ROWS];             // 32 MB  [k2][m] hi/lo bf16 pairs
__device__ uint2 g_WT[H * (INF_ / 2) * E];               // 4 MB   [h][k2][n]
__device__ uint2 g_WhT[(H * BN_ROWS / 2) * E];           // 32 MB  [word][e], word pairs rows (r, r+8) per 16-group
__device__ float g_f1a[H * BN_ROWS];                     // f1 accumulators (atomic)
__device__ float g_f2a[H * BN_ROWS];
__device__ float g_f1[H * BN_ROWS];
__device__ float g_E1[H * BN_ROWS];
__device__ float g_F1[H * BN_ROWS];
__device__ float4 g_pack[H * BN_ROWS];                   // (f2, exp(f2), exp(.2 f2), 0)
__device__ unsigned g_adjbits[Bb * Nn * (Nn / 32)];      // 1 MB packed adjacency
__device__ float g_feat[(size_t)BN_ROWS * H * E];        // 32 MB [row][h*E+e]

// ---- helpers ----
__device__ __forceinline__ uint32_t smem_u32(const void* p) {
    uint32_t a;
    asm("{ .reg .u64 t; cvta.to.shared.u64 t, %1; cvt.u32.u64 %0, t; }" : "=r"(a) : "l"(p));
    return a;
}
__device__ __forceinline__ uint32_t bfpack(float lo, float hi) {
    uint32_t r;
    asm("cvt.rn.bf16x2.f32 %0, %1, %2;" : "=r"(r) : "f"(hi), "f"(lo));
    return r;
}
__device__ __forceinline__ float bfres(float v) {
    return v - __bfloat162float(__float2bfloat16(v));
}
__device__ __forceinline__ uint2 split2(float a, float b) {
    uint2 r;
    r.x = bfpack(a, b);
    r.y = bfpack(bfres(a), bfres(b));
    return r;
}
__device__ __forceinline__ void cpa16(uint32_t dst, const void* src) {
    asm volatile("cp.async.cg.shared.global [%0], [%1], 16;" :: "r"(dst), "l"(src));
}
#define CP_COMMIT() asm volatile("cp.async.commit_group;" ::: "memory")
#define CP_WAIT0()  asm volatile("cp.async.wait_group 0;" ::: "memory")

__device__ __forceinline__ void mma16(float c[4], const uint32_t a[4], const uint32_t b[2]) {
    asm volatile(
        "mma.sync.aligned.m16n8k16.row.col.f32.bf16.bf16.f32 "
        "{%0,%1,%2,%3}, {%4,%5,%6,%7}, {%8,%9}, {%0,%1,%2,%3};"
        : "+f"(c[0]), "+f"(c[1]), "+f"(c[2]), "+f"(c[3])
        : "r"(a[0]), "r"(a[1]), "r"(a[2]), "r"(a[3]), "r"(b[0]), "r"(b[1]));
}

// one k16 step over 128x128: frags are uint2 (hi,lo) -> 24 LDS.64, 48 MMA
__device__ __forceinline__ void k16_step2(const uint2 (*A)[P2], const uint2 (*B)[P2],
                                          int k2, int mw, int nw, int lq, int lr,
                                          float acc[4][4][4]) {
    uint2 a[4][4], b[4][2];
#pragma unroll
    for (int mt = 0; mt < 4; mt++) {
        int m0 = mw + 16 * mt + lr;
        a[mt][0] = A[k2 + lq][m0];
        a[mt][1] = A[k2 + lq][m0 + 8];
        a[mt][2] = A[k2 + lq + 4][m0];
        a[mt][3] = A[k2 + lq + 4][m0 + 8];
    }
#pragma unroll
    for (int nt = 0; nt < 4; nt++) {
        int n0 = nw + 8 * nt + lr;
        b[nt][0] = B[k2 + lq][n0];
        b[nt][1] = B[k2 + lq + 4][n0];
    }
#pragma unroll
    for (int mt = 0; mt < 4; mt++) {
        uint32_t ah[4] = {a[mt][0].x, a[mt][1].x, a[mt][2].x, a[mt][3].x};
#pragma unroll
        for (int nt = 0; nt < 4; nt++) {
            uint32_t bh[2] = {b[nt][0].x, b[nt][1].x};
            mma16(acc[mt][nt], ah, bh);
        }
    }
#pragma unroll
    for (int mt = 0; mt < 4; mt++) {
        uint32_t ah[4] = {a[mt][0].x, a[mt][1].x, a[mt][2].x, a[mt][3].x};
#pragma unroll
        for (int nt = 0; nt < 4; nt++) {
            uint32_t bl[2] = {b[nt][0].y, b[nt][1].y};
            mma16(acc[mt][nt], ah, bl);
        }
    }
#pragma unroll
    for (int mt = 0; mt < 4; mt++) {
        uint32_t al[4] = {a[mt][0].y, a[mt][1].y, a[mt][2].y, a[mt][3].y};
#pragma unroll
        for (int nt = 0; nt < 4; nt++) {
            uint32_t bh[2] = {b[nt][0].x, b[nt][1].x};
            mma16(acc[mt][nt], al, bh);
        }
    }
}

#define GEMM_SMEM (4 * STAGE_B)
#define ATT_SMEM  (4 * STAGE_B + 1024)

// ============================================================
// K0: pack adjacency int32 -> bitmask; zero f accumulators
// ============================================================
__global__ void pack_adj(const int* __restrict__ adj) {
    int idx = blockIdx.x * blockDim.x + threadIdx.x;
    unsigned m = __ballot_sync(0xffffffffu, adj[idx] > 0);
    if ((idx & 31) == 0) g_adjbits[idx >> 5] = m;
    if (idx < H * BN_ROWS) { g_f1a[idx] = 0.f; g_f2a[idx] = 0.f; }
}

// ============================================================
// K0b: split+transpose x (8192x1024 f32) -> g_xT [512][8192] uint2
// ============================================================
__global__ void split_x(const float* __restrict__ x) {
    __shared__ uint2 ts[32][33];
    int m0 = blockIdx.x * 32, k20 = blockIdx.y * 32;
    int tx = threadIdx.x, ty = threadIdx.y;
    for (int r = ty; r < 32; r += 8) {
        float2 w = *(const float2*)(x + (size_t)(m0 + r) * INF_ + 2 * (k20 + tx));
        ts[tx][r] = split2(w.x, w.y);
    }
    __syncthreads();
    for (int r = ty; r < 32; r += 8)
        g_xT[(size_t)(k20 + r) * BN_ROWS + m0 + tx] = ts[r][tx];
}

// ============================================================
// K0c: split W (H,1024,256) -> g_WT [h][512][256] uint2 (adjacent k rows)
// ============================================================
__global__ void split_W(const float* __restrict__ W) {
    int idx = blockIdx.x * blockDim.x + threadIdx.x;    // H*512*64
    int p = idx >> 6;                                    // h*512 + k2
    int n4 = (idx & 63) * 4;
    const float* r0 = W + (size_t)(2 * p) * E + n4;
    const float* r1 = r0 + E;
    float4 u = *(const float4*)r0;
    float4 v = *(const float4*)r1;
    uint2* o = g_WT + (size_t)p * E + n4;
    o[0] = split2(u.x, v.x);
    o[1] = split2(u.y, v.y);
    o[2] = split2(u.z, v.z);
    o[3] = split2(u.w, v.w);
}

// ============================================================
// K1: Wh = x @ W[h], bf16x3 mma, cp.async double-buffered BK=32.
// Epilogue: split store to g_WhT + fused f1/f2 partial dot-products.
// grid (E/128=2, BN/128=64, H=4), 256 thr.
// ============================================================
__global__ void __launch_bounds__(256, 2) wh_gemm_mma(const float* __restrict__ a1,
                                                      const float* __restrict__ a2) {
    extern __shared__ uint2 smw2[];
    uint32_t sb = smem_u32(smw2);
    const uint2 (*Abuf)[P2] = (const uint2 (*)[P2])smw2;            // 2 stages x 16 rows
    const uint2 (*Bbuf)[P2] = (const uint2 (*)[P2])(smw2 + 2 * 16 * P2);
    uint32_t sbB = sb + 2 * STAGE_B;
    int h = blockIdx.z;
    int rowBase = blockIdx.y * 128;
    int colBase = blockIdx.x * 128;
    int tid = threadIdx.x, lane = tid & 31, wid = tid >> 5;
    int lq = lane & 3, lr = lane >> 2;
    int mw = (wid & 1) * 64, nw = (wid >> 1) * 32;

    const uint2* Asrc = g_xT + rowBase;                 // + k2*8192
    const uint2* Bsrc = g_WT + (size_t)h * 512 * E + colBase;

#define WH_LOAD(S, K2B)                                                        \
    do {                                                                       \
        _Pragma("unroll")                                                      \
        for (int t = tid; t < 1024; t += 256) {                                \
            int r = t >> 6, q = t & 63;                                        \
            cpa16(sb + (S) * STAGE_B + r * ROWB + q * 16,                      \
                  (const char*)(Asrc + (size_t)((K2B) + r) * BN_ROWS) + q * 16); \
            cpa16(sbB + (S) * STAGE_B + r * ROWB + q * 16,                     \
                  (const char*)(Bsrc + (size_t)((K2B) + r) * E) + q * 16);     \
        }                                                                      \
    } while (0)

#define WH_ITER(CB, NB, C)                                                     \
    do {                                                                       \
        if ((C) < 31) { WH_LOAD(NB, ((C) + 1) * 16); CP_COMMIT(); }            \
        k16_step2(Abuf + (CB) * 16, Bbuf + (CB) * 16, 0, mw, nw, lq, lr, acc); \
        k16_step2(Abuf + (CB) * 16, Bbuf + (CB) * 16, 8, mw, nw, lq, lr, acc); \
        if ((C) < 31) CP_WAIT0();                                              \
        __syncthreads();                                                       \
    } while (0)

    WH_LOAD(0, 0);
    CP_COMMIT();
    CP_WAIT0();
    __syncthreads();

    float acc[4][4][4] = {};
    for (int c2 = 0; c2 < 16; c2++) {
        WH_ITER(0, 1, 2 * c2);
        WH_ITER(1, 0, 2 * c2 + 1);
    }
#undef WH_ITER
#undef WH_LOAD

    // ---- epilogue: g_WhT split store + fused f1/f2 partials ----
    float* f1s = (float*)smw2;          // reuse pipeline smem
    float* f2s = f1s + 128;
    if (tid < 128) { f1s[tid] = 0.f; f2s[tid] = 0.f; }
    __syncthreads();
    const float* a1p = a1 + h * E + colBase;
    const float* a2p = a2 + h * E + colBase;
#pragma unroll
    for (int mt = 0; mt < 4; mt++) {
        int rl = mw + 16 * mt + lr;
        size_t wword = ((size_t)h * BN_ROWS + rowBase + mw + 16 * mt) / 2 + lr;
        float p10 = 0.f, p20 = 0.f, p18 = 0.f, p28 = 0.f;
#pragma unroll
        for (int nt = 0; nt < 4; nt++) {
            int cc = nw + 8 * nt + 2 * lq;
            g_WhT[wword * E + colBase + cc]     = split2(acc[mt][nt][0], acc[mt][nt][2]);
            g_WhT[wword * E + colBase + cc + 1] = split2(acc[mt][nt][1], acc[mt][nt][3]);
            float a10 = a1p[cc], a11 = a1p[cc + 1];
            float a20 = a2p[cc], a21 = a2p[cc + 1];
            p10 += acc[mt][nt][0] * a10 + acc[mt][nt][1] * a11;
            p20 += acc[mt][nt][0] * a20 + acc[mt][nt][1] * a21;
            p18 += acc[mt][nt][2] * a10 + acc[mt][nt][3] * a11;
            p28 += acc[mt][nt][2] * a20 + acc[mt][nt][3] * a21;
        }
        p10 += __shfl_xor_sync(0xffffffffu, p10, 1);
        p10 += __shfl_xor_sync(0xffffffffu, p10, 2);
        p20 += __shfl_xor_sync(0xffffffffu, p20, 1);
        p20 += __shfl_xor_sync(0xffffffffu, p20, 2);
        p18 += __shfl_xor_sync(0xffffffffu, p18, 1);
        p18 += __shfl_xor_sync(0xffffffffu, p18, 2);
        p28 += __shfl_xor_sync(0xffffffffu, p28, 1);
        p28 += __shfl_xor_sync(0xffffffffu, p28, 2);
        if (lq == 0) {
            atomicAdd(&f1s[rl], p10);
            atomicAdd(&f2s[rl], p20);
            atomicAdd(&f1s[rl + 8], p18);
            atomicAdd(&f2s[rl + 8], p28);
        }
    }
    __syncthreads();
    if (tid < 128) {
        atomicAdd(&g_f1a[h * BN_ROWS + rowBase + tid], f1s[tid]);
        atomicAdd(&g_f2a[h * BN_ROWS + rowBase + tid], f2s[tid]);
    }
}

// ============================================================
// K2: exp_f — build E1/F1/pack from accumulated f1/f2
// ============================================================
__global__ void exp_f() {
    int r = blockIdx.x * blockDim.x + threadIdx.x;
    float s1 = g_f1a[r], s2 = g_f2a[r];
    g_f1[r] = s1;
    g_E1[r] = __expf(s1);
    g_F1[r] = __expf(ALPHA * s1);
    g_pack[r] = make_float4(s2, __expf(s2), __expf(ALPHA * s2), 0.f);
}

// ============================================================
// K3: h' = att @ Wh_b, bf16x3 mma; A generated on the fly with the
// (j, j+8) 16-group pairing matching g_WhT; B via cp.async.
// grid (E/128=2, Nn/128=8, H*Bb=32), 256 thr.
// ============================================================
__global__ void __launch_bounds__(256, 2) att_gemm_mma() {
    extern __shared__ uint2 smw2[];
    uint32_t sb = smem_u32(smw2);
    uint2 (*Abuf)[P2] = (uint2 (*)[P2])smw2;
    const uint2 (*Bbuf)[P2] = (const uint2 (*)[P2])(smw2 + 2 * 16 * P2);
    uint32_t sbB = sb + 2 * STAGE_B;
    float* Ssum = (float*)(smw2 + 4 * 16 * P2);       // [2][128]
    int hb = blockIdx.z;
    int h = hb >> 3, b = hb & 7;
    int rowBase = blockIdx.y * 128;
    int colBase = blockIdx.x * 128;
    int base = h * BN_ROWS + b * Nn;
    int tid = threadIdx.x, lane = tid & 31, wid = tid >> 5;
    int lq = lane & 3, lr = lane >> 2;
    int mw = (wid & 1) * 64, nw = (wid >> 1) * 32;

    int ig = tid & 127;
    int jp = tid >> 7;
    int gi = base + rowBase + ig;
    float f1v = g_f1[gi], E1v = g_E1[gi], F1v = g_F1[gi];
    const unsigned* awp = g_adjbits + (size_t)(b * Nn + rowBase + ig) * (Nn / 32);
    float rsum = 0.f;

    const uint2* Bsrc = g_WhT + (size_t)((h * BN_ROWS + b * Nn) >> 1) * E + colBase;

#define ATT_BLOAD(S, K2B)                                                      \
    do {                                                                       \
        _Pragma("unroll")                                                      \
        for (int t = tid; t < 1024; t += 256) {                                \
            int r = t >> 6, q = t & 63;                                        \
            cpa16(sbB + (S) * STAGE_B + r * ROWB + q * 16,                     \
                  (const char*)(Bsrc + (size_t)((K2B) + r) * E) + q * 16);     \
        }                                                                      \
    } while (0)

// word w = 8*jp + t packs js (K0 + 16*jp + t) and (K0 + 16*jp + t + 8)
#define GENA(S, K0)                                                            \
    do {                                                                       \
        unsigned wb = awp[(K0) >> 5] >> (16 * jp);                             \
        _Pragma("unroll")                                                      \
        for (int t = 0; t < 8; t++) {                                          \
            int j = (K0) + 16 * jp + t;                                        \
            float4 p0 = g_pack[base + j];                                      \
            float4 p1 = g_pack[base + j + 8];                                  \
            float s0 = f1v + p0.x;                                             \
            float v0 = ((wb >> t) & 1u)                                        \
                           ? ((s0 > 0.f) ? E1v * p0.y : F1v * p0.z) : 0.f;     \
            float s1 = f1v + p1.x;                                             \
            float v1 = ((wb >> (t + 8)) & 1u)                                  \
                           ? ((s1 > 0.f) ? E1v * p1.y : F1v * p1.z) : 0.f;     \
            rsum += v0 + v1;                                                   \
            Abuf[(S) * 16 + 8 * jp + t][ig] = split2(v0, v1);                  \
        }                                                                      \
    } while (0)

#define ATT_ITER(CB, NB, C)                                                    \
    do {                                                                       \
        if ((C) < 31) { ATT_BLOAD(NB, ((C) + 1) * 16); CP_COMMIT(); }          \
        k16_step2((const uint2 (*)[P2])(Abuf + (CB) * 16), Bbuf + (CB) * 16,   \
                  0, mw, nw, lq, lr, acc);                                     \
        if ((C) < 31) GENA(NB, ((C) + 1) * 32);                                \
        k16_step2((const uint2 (*)[P2])(Abuf + (CB) * 16), Bbuf + (CB) * 16,   \
                  8, mw, nw, lq, lr, acc);                                     \
        if ((C) < 31) CP_WAIT0();                                              \
        __syncthreads();                                                       \
    } while (0)

    // prologue
    ATT_BLOAD(0, 0);
    CP_COMMIT();
    GENA(0, 0);
    CP_WAIT0();
    __syncthreads();

    float acc[4][4][4] = {};
    for (int c2 = 0; c2 < 16; c2++) {
        ATT_ITER(0, 1, 2 * c2);
        ATT_ITER(1, 0, 2 * c2 + 1);
    }
#undef ATT_ITER
#undef GENA
#undef ATT_BLOAD

    Ssum[jp * 128 + ig] = rsum;
    __syncthreads();

#pragma unroll
    for (int mt = 0; mt < 4; mt++) {
        int rl = mw + 16 * mt + lr;
        float S0 = Ssum[rl] + Ssum[128 + rl];
        float S8 = Ssum[rl + 8] + Ssum[128 + rl + 8];
        float sc0 = (S0 > 0.f) ? (1.0f / S0) : 0.f;
        float sc8 = (S8 > 0.f) ? (1.0f / S8) : 0.f;
        float* f0 = g_feat + (size_t)(b * Nn + rowBase + rl) * (H * E) + h * E + colBase;
        float* f8 = g_feat + (size_t)(b * Nn + rowBase + rl + 8) * (H * E) + h * E + colBase;
#pragma unroll
        for (int nt = 0; nt < 4; nt++) {
            int cc = nw + 8 * nt + 2 * lq;
            float v0 = acc[mt][nt][0] * sc0;
            float v1 = acc[mt][nt][1] * sc0;
            float v2 = acc[mt][nt][2] * sc8;
            float v3 = acc[mt][nt][3] * sc8;
            v0 = (v0 > 0.f) ? v0 : expm1f(v0);
            v1 = (v1 > 0.f) ? v1 : expm1f(v1);
            v2 = (v2 > 0.f) ? v2 : expm1f(v2);
            v3 = (v3 > 0.f) ? v3 : expm1f(v3);
            *(float2*)(f0 + cc) = make_float2(v0, v1);
            *(float2*)(f8 + cc) = make_float2(v2, v3);
        }
    }
}

// ============================================================
// K5: out (8192x64) = feat (8192x1024) @ W_act (1024x64) + b_act
// ============================================================
__global__ void __launch_bounds__(256) final_gemm(const float* __restrict__ W_act,
                                                  const float* __restrict__ b_act,
                                                  float* __restrict__ out) {
    __shared__ float As[16][34];
    __shared__ float Bs[16][68];
    int rowBase = blockIdx.y * 32;
    int tid = threadIdx.x;
    int tx = tid & 15, ty = tid >> 4;
    float acc[2][4] = {};
    for (int k0 = 0; k0 < H * E; k0 += 16) {
        if (tid < 128) {
            int r = tid >> 2, ch = tid & 3;
            float4 v = *(const float4*)(g_feat + (size_t)(rowBase + r) * (H * E) + k0 + 4 * ch);
            As[4 * ch + 0][r] = v.x; As[4 * ch + 1][r] = v.y;
            As[4 * ch + 2][r] = v.z; As[4 * ch + 3][r] = v.w;
        }
        {
            int r = tid >> 4, ch = tid & 15;
            float4 v = *(const float4*)(W_act + (size_t)(k0 + r) * A_ + 4 * ch);
            *(float4*)&Bs[r][4 * ch] = v;
        }
        __syncthreads();
#pragma unroll
        for (int kk = 0; kk < 16; kk++) {
            float a0 = As[kk][ty * 2], a1v = As[kk][ty * 2 + 1];
            float4 bv = *(float4*)&Bs[kk][tx * 4];
            acc[0][0] += a0 * bv.x; acc[0][1] += a0 * bv.y;
            acc[0][2] += a0 * bv.z; acc[0][3] += a0 * bv.w;
            acc[1][0] += a1v * bv.x; acc[1][1] += a1v * bv.y;
            acc[1][2] += a1v * bv.z; acc[1][3] += a1v * bv.w;
        }
        __syncthreads();
    }
    float4 bias = *(const float4*)(b_act + tx * 4);
#pragma unroll
    for (int i = 0; i < 2; i++) {
        int r = rowBase + ty * 2 + i;
        float4 v = make_float4(acc[i][0] + bias.x, acc[i][1] + bias.y,
                               acc[i][2] + bias.z, acc[i][3] + bias.w);
        *(float4*)(out + (size_t)r * A_ + tx * 4) = v;
    }
}

extern "C" void kernel_launch(void* const* d_in, const int* in_sizes, int n_in,
                              void* d_out, int out_size) {
    const float* x     = (const float*)d_in[0];
    const int*   adj   = (const int*)d_in[1];
    const float* W     = (const float*)d_in[2];
    const float* a1    = (const float*)d_in[3];
    const float* a2    = (const float*)d_in[4];
    const float* W_act = (const float*)d_in[5];
    const float* b_act = (const float*)d_in[6];
    float* out = (float*)d_out;

    cudaFuncSetAttribute(wh_gemm_mma, cudaFuncAttributeMaxDynamicSharedMemorySize, GEMM_SMEM);
    cudaFuncSetAttribute(att_gemm_mma, cudaFuncAttributeMaxDynamicSharedMemorySize, ATT_SMEM);

    pack_adj<<<(Bb * Nn * Nn) / 256, 256>>>(adj);
    split_x<<<dim3(BN_ROWS / 32, (INF_ / 2) / 32), dim3(32, 8)>>>(x);
    split_W<<<(H * (INF_ / 2) * (E / 4)) / 256, 256>>>(W);
    wh_gemm_mma<<<dim3(E / 128, BN_ROWS / 128, H), 256, GEMM_SMEM>>>(a1, a2);
    exp_f<<<(H * BN_ROWS) / 256, 256>>>();
    att_gemm_mma<<<dim3(E / 128, Nn / 128, H * Bb), 256, ATT_SMEM>>>();
    final_gemm<<<dim3(1, BN_ROWS / 32), 256>>>(W_act, b_act, out);
}

// round 14
// speedup vs baseline: 1.6185x; 1.0221x over previous
#include <cuda_runtime.h>
#include <cuda_bf16.h>
#include <math.h>
#include <stdint.h>

#define H 4
#define Bb 8
#define Nn 1024
#define INF_ 1024
#define E 256
#define A_ 64
#define BN_ROWS 8192        /* B*N */
#define ALPHA 0.2f
#define P2 132              /* smem row pitch in uint2 (1056B: +8 banks/row) */
#define ROWB 1056           /* P2 * 8 bytes */
#define STAGE_B 16896       /* 16 rows * 1056B */

// ---- scratch (static device memory; no runtime allocation) ----
__device__ uint2 g_xT[(INF_ / 2) * BN_ROWS];             // 32 MB  [k2][m] hi/lo bf16 pairs
__device__ uint2 g_WT[H * (INF_ / 2) * E];               // 4 MB   [h][k2][n]
__device__ uint2 g_WhT[(H * BN_ROWS / 2) * E];           // 32 MB  [word][e], word pairs rows (r, r+8) per 16-group
__device__ float g_f1a[H * BN_ROWS];                     // f1 accumulators (atomic)
__device__ float g_f2a[H * BN_ROWS];
__device__ float g_f1[H * BN_ROWS];
__device__ float g_E1[H * BN_ROWS];
__device__ float g_F1[H * BN_ROWS];
__device__ float4 g_pack[H * BN_ROWS];                   // (f2, exp(f2), exp(.2 f2), 0)
__device__ unsigned g_adjbits[Bb * Nn * (Nn / 32)];      // 1 MB packed adjacency
__device__ float g_feat[(size_t)BN_ROWS * H * E];        // 32 MB [row][h*E+e]

// ---- helpers ----
__device__ __forceinline__ uint32_t smem_u32(const void* p) {
    uint32_t a;
    asm("{ .reg .u64 t; cvta.to.shared.u64 t, %1; cvt.u32.u64 %0, t; }" : "=r"(a) : "l"(p));
    return a;
}
__device__ __forceinline__ uint32_t bfpack(float lo, float hi) {
    uint32_t r;
    asm("cvt.rn.bf16x2.f32 %0, %1, %2;" : "=r"(r) : "f"(hi), "f"(lo));
    return r;
}
__device__ __forceinline__ float bfres(float v) {
    return v - __bfloat162float(__float2bfloat16(v));
}
__device__ __forceinline__ uint2 split2(float a, float b) {
    uint2 r;
    r.x = bfpack(a, b);
    r.y = bfpack(bfres(a), bfres(b));
    return r;
}
__device__ __forceinline__ void cpa16(uint32_t dst, const void* src) {
    asm volatile("cp.async.cg.shared.global [%0], [%1], 16;" :: "r"(dst), "l"(src));
}
#define CP_COMMIT() asm volatile("cp.async.commit_group;" ::: "memory")
#define CP_WAIT0()  asm volatile("cp.async.wait_group 0;" ::: "memory")

// direct-operand mma: no temp operand arrays -> no MOV staging
__device__ __forceinline__ void mma16s(float c[4],
                                       uint32_t a0, uint32_t a1, uint32_t a2, uint32_t a3,
                                       uint32_t b0, uint32_t b1) {
    asm volatile(
        "mma.sync.aligned.m16n8k16.row.col.f32.bf16.bf16.f32 "
        "{%0,%1,%2,%3}, {%4,%5,%6,%7}, {%8,%9}, {%0,%1,%2,%3};"
        : "+f"(c[0]), "+f"(c[1]), "+f"(c[2]), "+f"(c[3])
        : "r"(a0), "r"(a1), "r"(a2), "r"(a3), "r"(b0), "r"(b1));
}

// one k16 step over 128x128: frags are uint2 (hi,lo) -> 24 LDS.64, 48 MMA
__device__ __forceinline__ void k16_step2(const uint2 (*A)[P2], const uint2 (*B)[P2],
                                          int k2, int mw, int nw, int lq, int lr,
                                          float acc[4][4][4]) {
    uint2 a[4][4], b[4][2];
#pragma unroll
    for (int mt = 0; mt < 4; mt++) {
        int m0 = mw + 16 * mt + lr;
        a[mt][0] = A[k2 + lq][m0];
        a[mt][1] = A[k2 + lq][m0 + 8];
        a[mt][2] = A[k2 + lq + 4][m0];
        a[mt][3] = A[k2 + lq + 4][m0 + 8];
    }
#pragma unroll
    for (int nt = 0; nt < 4; nt++) {
        int n0 = nw + 8 * nt + lr;
        b[nt][0] = B[k2 + lq][n0];
        b[nt][1] = B[k2 + lq + 4][n0];
    }
#pragma unroll
    for (int mt = 0; mt < 4; mt++)
#pragma unroll
        for (int nt = 0; nt < 4; nt++)
            mma16s(acc[mt][nt], a[mt][0].x, a[mt][1].x, a[mt][2].x, a[mt][3].x,
                   b[nt][0].x, b[nt][1].x);
#pragma unroll
    for (int mt = 0; mt < 4; mt++)
#pragma unroll
        for (int nt = 0; nt < 4; nt++)
            mma16s(acc[mt][nt], a[mt][0].x, a[mt][1].x, a[mt][2].x, a[mt][3].x,
                   b[nt][0].y, b[nt][1].y);
#pragma unroll
    for (int mt = 0; mt < 4; mt++)
#pragma unroll
        for (int nt = 0; nt < 4; nt++)
            mma16s(acc[mt][nt], a[mt][0].y, a[mt][1].y, a[mt][2].y, a[mt][3].y,
                   b[nt][0].x, b[nt][1].x);
}

#define GEMM_SMEM (4 * STAGE_B)
#define ATT_SMEM  (4 * STAGE_B + 1024)

// ============================================================
// K0: pack adjacency int32 -> bitmask; zero f accumulators
// ============================================================
__global__ void pack_adj(const int* __restrict__ adj) {
    int idx = blockIdx.x * blockDim.x + threadIdx.x;
    unsigned m = __ballot_sync(0xffffffffu, adj[idx] > 0);
    if ((idx & 31) == 0) g_adjbits[idx >> 5] = m;
    if (idx < H * BN_ROWS) { g_f1a[idx] = 0.f; g_f2a[idx] = 0.f; }
}

// ============================================================
// K0b: split+transpose x (8192x1024 f32) -> g_xT [512][8192] uint2
// ============================================================
__global__ void split_x(const float* __restrict__ x) {
    __shared__ uint2 ts[32][33];
    int m0 = blockIdx.x * 32, k20 = blockIdx.y * 32;
    int tx = threadIdx.x, ty = threadIdx.y;
    for (int r = ty; r < 32; r += 8) {
        float2 w = *(const float2*)(x + (size_t)(m0 + r) * INF_ + 2 * (k20 + tx));
        ts[tx][r] = split2(w.x, w.y);
    }
    __syncthreads();
    for (int r = ty; r < 32; r += 8)
        g_xT[(size_t)(k20 + r) * BN_ROWS + m0 + tx] = ts[r][tx];
}

// ============================================================
// K0c: split W (H,1024,256) -> g_WT [h][512][256] uint2 (adjacent k rows)
// ============================================================
__global__ void split_W(const float* __restrict__ W) {
    int idx = blockIdx.x * blockDim.x + threadIdx.x;    // H*512*64
    int p = idx >> 6;                                    // h*512 + k2
    int n4 = (idx & 63) * 4;
    const float* r0 = W + (size_t)(2 * p) * E + n4;
    const float* r1 = r0 + E;
    float4 u = *(const float4*)r0;
    float4 v = *(const float4*)r1;
    uint2* o = g_WT + (size_t)p * E + n4;
    o[0] = split2(u.x, v.x);
    o[1] = split2(u.y, v.y);
    o[2] = split2(u.z, v.z);
    o[3] = split2(u.w, v.w);
}

// ============================================================
// K1: Wh = x @ W[h], bf16x3 mma, cp.async double-buffered BK=32.
// Epilogue: split store to g_WhT + fused f1/f2 partial dot-products.
// grid (E/128=2, BN/128=64, H=4), 256 thr.
// ============================================================
__global__ void __launch_bounds__(256, 2) wh_gemm_mma(const float* __restrict__ a1,
                                                      const float* __restrict__ a2) {
    extern __shared__ uint2 smw2[];
    uint32_t sb = smem_u32(smw2);
    const uint2 (*Abuf)[P2] = (const uint2 (*)[P2])smw2;            // 2 stages x 16 rows
    const uint2 (*Bbuf)[P2] = (const uint2 (*)[P2])(smw2 + 2 * 16 * P2);
    uint32_t sbB = sb + 2 * STAGE_B;
    int h = blockIdx.z;
    int rowBase = blockIdx.y * 128;
    int colBase = blockIdx.x * 128;
    int tid = threadIdx.x, lane = tid & 31, wid = tid >> 5;
    int lq = lane & 3, lr = lane >> 2;
    int mw = (wid & 1) * 64, nw = (wid >> 1) * 32;

    const uint2* Asrc = g_xT + rowBase;                 // + k2*8192
    const uint2* Bsrc = g_WT + (size_t)h * 512 * E + colBase;

#define WH_LOAD(S, K2B)                                                        \
    do {                                                                       \
        _Pragma("unroll")                                                      \
        for (int t = tid; t < 1024; t += 256) {                                \
            int r = t >> 6, q = t & 63;                                        \
            cpa16(sb + (S) * STAGE_B + r * ROWB + q * 16,                      \
                  (const char*)(Asrc + (size_t)((K2B) + r) * BN_ROWS) + q * 16); \
            cpa16(sbB + (S) * STAGE_B + r * ROWB + q * 16,                     \
                  (const char*)(Bsrc + (size_t)((K2B) + r) * E) + q * 16);     \
        }                                                                      \
    } while (0)

#define WH_ITER(CB, NB, C)                                                     \
    do {                                                                       \
        if ((C) < 31) { WH_LOAD(NB, ((C) + 1) * 16); CP_COMMIT(); }            \
        k16_step2(Abuf + (CB) * 16, Bbuf + (CB) * 16, 0, mw, nw, lq, lr, acc); \
        k16_step2(Abuf + (CB) * 16, Bbuf + (CB) * 16, 8, mw, nw, lq, lr, acc); \
        if ((C) < 31) CP_WAIT0();                                              \
        __syncthreads();                                                       \
    } while (0)

    WH_LOAD(0, 0);
    CP_COMMIT();
    CP_WAIT0();
    __syncthreads();

    float acc[4][4][4] = {};
    for (int c2 = 0; c2 < 16; c2++) {
        WH_ITER(0, 1, 2 * c2);
        WH_ITER(1, 0, 2 * c2 + 1);
    }
#undef WH_ITER
#undef WH_LOAD

    // ---- epilogue: g_WhT split store + fused f1/f2 partials ----
    float* f1s = (float*)smw2;          // reuse pipeline smem
    float* f2s = f1s + 128;
    if (tid < 128) { f1s[tid] = 0.f; f2s[tid] = 0.f; }
    __syncthreads();
    const float* a1p = a1 + h * E + colBase;
    const float* a2p = a2 + h * E + colBase;
#pragma unroll
    for (int mt = 0; mt < 4; mt++) {
        int rl = mw + 16 * mt + lr;
        size_t wword = ((size_t)h * BN_ROWS + rowBase + mw + 16 * mt) / 2 + lr;
        float p10 = 0.f, p20 = 0.f, p18 = 0.f, p28 = 0.f;
#pragma unroll
        for (int nt = 0; nt < 4; nt++) {
            int cc = nw + 8 * nt + 2 * lq;
            g_WhT[wword * E + colBase + cc]     = split2(acc[mt][nt][0], acc[mt][nt][2]);
            g_WhT[wword * E + colBase + cc + 1] = split2(acc[mt][nt][1], acc[mt][nt][3]);
            float a10 = a1p[cc], a11 = a1p[cc + 1];
            float a20 = a2p[cc], a21 = a2p[cc + 1];
            p10 += acc[mt][nt][0] * a10 + acc[mt][nt][1] * a11;
            p20 += acc[mt][nt][0] * a20 + acc[mt][nt][1] * a21;
            p18 += acc[mt][nt][2] * a10 + acc[mt][nt][3] * a11;
            p28 += acc[mt][nt][2] * a20 + acc[mt][nt][3] * a21;
        }
        p10 += __shfl_xor_sync(0xffffffffu, p10, 1);
        p10 += __shfl_xor_sync(0xffffffffu, p10, 2);
        p20 += __shfl_xor_sync(0xffffffffu, p20, 1);
        p20 += __shfl_xor_sync(0xffffffffu, p20, 2);
        p18 += __shfl_xor_sync(0xffffffffu, p18, 1);
        p18 += __shfl_xor_sync(0xffffffffu, p18, 2);
        p28 += __shfl_xor_sync(0xffffffffu, p28, 1);
        p28 += __shfl_xor_sync(0xffffffffu, p28, 2);
        if (lq == 0) {
            atomicAdd(&f1s[rl], p10);
            atomicAdd(&f2s[rl], p20);
            atomicAdd(&f1s[rl + 8], p18);
            atomicAdd(&f2s[rl + 8], p28);
        }
    }
    __syncthreads();
    if (tid < 128) {
        atomicAdd(&g_f1a[h * BN_ROWS + rowBase + tid], f1s[tid]);
        atomicAdd(&g_f2a[h * BN_ROWS + rowBase + tid], f2s[tid]);
    }
}

// ============================================================
// K2: exp_f — build E1/F1/pack from accumulated f1/f2
// ============================================================
__global__ void exp_f() {
    int r = blockIdx.x * blockDim.x + threadIdx.x;
    float s1 = g_f1a[r], s2 = g_f2a[r];
    g_f1[r] = s1;
    g_E1[r] = __expf(s1);
    g_F1[r] = __expf(ALPHA * s1);
    g_pack[r] = make_float4(s2, __expf(s2), __expf(ALPHA * s2), 0.f);
}

// ============================================================
// K3: h' = att @ Wh_b, bf16x3 mma; A generated on the fly with the
// (j, j+8) 16-group pairing matching g_WhT; B via cp.async.
// grid (E/128=2, Nn/128=8, H*Bb=32), 256 thr.
// ============================================================
__global__ void __launch_bounds__(256, 2) att_gemm_mma() {
    extern __shared__ uint2 smw2[];
    uint32_t sb = smem_u32(smw2);
    uint2 (*Abuf)[P2] = (uint2 (*)[P2])smw2;
    const uint2 (*Bbuf)[P2] = (const uint2 (*)[P2])(smw2 + 2 * 16 * P2);
    uint32_t sbB = sb + 2 * STAGE_B;
    float* Ssum = (float*)(smw2 + 4 * 16 * P2);       // [2][128]
    int hb = blockIdx.z;
    int h = hb >> 3, b = hb & 7;
    int rowBase = blockIdx.y * 128;
    int colBase = blockIdx.x * 128;
    int base = h * BN_ROWS + b * Nn;
    int tid = threadIdx.x, lane = tid & 31, wid = tid >> 5;
    int lq = lane & 3, lr = lane >> 2;
    int mw = (wid & 1) * 64, nw = (wid >> 1) * 32;

    int ig = tid & 127;
    int jp = tid >> 7;
    int gi = base + rowBase + ig;
    float f1v = g_f1[gi], E1v = g_E1[gi], F1v = g_F1[gi];
    const unsigned* awp = g_adjbits + (size_t)(b * Nn + rowBase + ig) * (Nn / 32);
    float rsum = 0.f;

    const uint2* Bsrc = g_WhT + (size_t)((h * BN_ROWS + b * Nn) >> 1) * E + colBase;

#define ATT_BLOAD(S, K2B)                                                      \
    do {                                                                       \
        _Pragma("unroll")                                                      \
        for (int t = tid; t < 1024; t += 256) {                                \
            int r = t >> 6, q = t & 63;                                        \
            cpa16(sbB + (S) * STAGE_B + r * ROWB + q * 16,                     \
                  (const char*)(Bsrc + (size_t)((K2B) + r) * E) + q * 16);     \
        }                                                                      \
    } while (0)

// word w = 8*jp + t packs js (K0 + 16*jp + t) and (K0 + 16*jp + t + 8)
#define GENA(S, K0)                                                            \
    do {                                                                       \
        unsigned wb = awp[(K0) >> 5] >> (16 * jp);                             \
        _Pragma("unroll")                                                      \
        for (int t = 0; t < 8; t++) {                                          \
            int j = (K0) + 16 * jp + t;                                        \
            float4 p0 = g_pack[base + j];                                      \
            float4 p1 = g_pack[base + j + 8];                                  \
            float s0 = f1v + p0.x;                                             \
            float v0 = ((wb >> t) & 1u)                                        \
                           ? ((s0 > 0.f) ? E1v * p0.y : F1v * p0.z) : 0.f;     \
            float s1 = f1v + p1.x;                                             \
            float v1 = ((wb >> (t + 8)) & 1u)                                  \
                           ? ((s1 > 0.f) ? E1v * p1.y : F1v * p1.z) : 0.f;     \
            rsum += v0 + v1;                                                   \
            Abuf[(S) * 16 + 8 * jp + t][ig] = split2(v0, v1);                  \
        }                                                                      \
    } while (0)

#define ATT_ITER(CB, NB, C)                                                    \
    do {                                                                       \
        if ((C) < 31) { ATT_BLOAD(NB, ((C) + 1) * 16); CP_COMMIT(); }          \
        k16_step2((const uint2 (*)[P2])(Abuf + (CB) * 16), Bbuf + (CB) * 16,   \
                  0, mw, nw, lq, lr, acc);                                     \
        if ((C) < 31) GENA(NB, ((C) + 1) * 32);                                \
        k16_step2((const uint2 (*)[P2])(Abuf + (CB) * 16), Bbuf + (CB) * 16,   \
                  8, mw, nw, lq, lr, acc);                                     \
        if ((C) < 31) CP_WAIT0();                                              \
        __syncthreads();                                                       \
    } while (0)

    // prologue
    ATT_BLOAD(0, 0);
    CP_COMMIT();
    GENA(0, 0);
    CP_WAIT0();
    __syncthreads();

    float acc[4][4][4] = {};
    for (int c2 = 0; c2 < 16; c2++) {
        ATT_ITER(0, 1, 2 * c2);
        ATT_ITER(1, 0, 2 * c2 + 1);
    }
#undef ATT_ITER
#undef GENA
#undef ATT_BLOAD

    Ssum[jp * 128 + ig] = rsum;
    __syncthreads();

#pragma unroll
    for (int mt = 0; mt < 4; mt++) {
        int rl = mw + 16 * mt + lr;
        float S0 = Ssum[rl] + Ssum[128 + rl];
        float S8 = Ssum[rl + 8] + Ssum[128 + rl + 8];
        float sc0 = (S0 > 0.f) ? (1.0f / S0) : 0.f;
        float sc8 = (S8 > 0.f) ? (1.0f / S8) : 0.f;
        float* f0 = g_feat + (size_t)(b * Nn + rowBase + rl) * (H * E) + h * E + colBase;
        float* f8 = g_feat + (size_t)(b * Nn + rowBase + rl + 8) * (H * E) + h * E + colBase;
#pragma unroll
        for (int nt = 0; nt < 4; nt++) {
            int cc = nw + 8 * nt + 2 * lq;
            float v0 = acc[mt][nt][0] * sc0;
            float v1 = acc[mt][nt][1] * sc0;
            float v2 = acc[mt][nt][2] * sc8;
            float v3 = acc[mt][nt][3] * sc8;
            v0 = (v0 > 0.f) ? v0 : expm1f(v0);
            v1 = (v1 > 0.f) ? v1 : expm1f(v1);
            v2 = (v2 > 0.f) ? v2 : expm1f(v2);
            v3 = (v3 > 0.f) ? v3 : expm1f(v3);
            *(float2*)(f0 + cc) = make_float2(v0, v1);
            *(float2*)(f8 + cc) = make_float2(v2, v3);
        }
    }
}

// ============================================================
// K5: out (8192x64) = feat (8192x1024) @ W_act (1024x64) + b_act
// BM=64, 4x4 microtile, 256 thr; grid 128
// ============================================================
__global__ void __launch_bounds__(256) final_gemm(const float* __restrict__ W_act,
                                                  const float* __restrict__ b_act,
                                                  float* __restrict__ out) {
    __shared__ float As[16][68];
    __shared__ float Bs[16][68];
    int rowBase = blockIdx.y * 64;
    int tid = threadIdx.x;
    int tx = tid & 15, ty = tid >> 4;
    float acc[4][4] = {};
    for (int k0 = 0; k0 < H * E; k0 += 16) {
        {
            int r = tid >> 2, ch = tid & 3;
            float4 v = *(const float4*)(g_feat + (size_t)(rowBase + r) * (H * E) + k0 + 4 * ch);
            As[4 * ch + 0][r] = v.x; As[4 * ch + 1][r] = v.y;
            As[4 * ch + 2][r] = v.z; As[4 * ch + 3][r] = v.w;
        }
        {
            int r = tid >> 4, ch = tid & 15;
            float4 v = *(const float4*)(W_act + (size_t)(k0 + r) * A_ + 4 * ch);
            *(float4*)&Bs[r][4 * ch] = v;
        }
        __syncthreads();
#pragma unroll
        for (int kk = 0; kk < 16; kk++) {
            float4 av = *(float4*)&As[kk][ty * 4];
            float4 bv = *(float4*)&Bs[kk][tx * 4];
            float a[4] = {av.x, av.y, av.z, av.w};
            float bb[4] = {bv.x, bv.y, bv.z, bv.w};
#pragma unroll
            for (int i = 0; i < 4; i++)
#pragma unroll
                for (int j = 0; j < 4; j++) acc[i][j] += a[i] * bb[j];
        }
        __syncthreads();
    }
    float4 bias = *(const float4*)(b_act + tx * 4);
#pragma unroll
    for (int i = 0; i < 4; i++) {
        int r = rowBase + ty * 4 + i;
        float4 v = make_float4(acc[i][0] + bias.x, acc[i][1] + bias.y,
                               acc[i][2] + bias.z, acc[i][3] + bias.w);
        *(float4*)(out + (size_t)r * A_ + tx * 4) = v;
    }
}

extern "C" void kernel_launch(void* const* d_in, const int* in_sizes, int n_in,
                              void* d_out, int out_size) {
    const float* x     = (const float*)d_in[0];
    const int*   adj   = (const int*)d_in[1];
    const float* W     = (const float*)d_in[2];
    const float* a1    = (const float*)d_in[3];
    const float* a2    = (const float*)d_in[4];
    const float* W_act = (const float*)d_in[5];
    const float* b_act = (const float*)d_in[6];
    float* out = (float*)d_out;

    cudaFuncSetAttribute(wh_gemm_mma, cudaFuncAttributeMaxDynamicSharedMemorySize, GEMM_SMEM);
    cudaFuncSetAttribute(att_gemm_mma, cudaFuncAttributeMaxDynamicSharedMemorySize, ATT_SMEM);

    pack_adj<<<(Bb * Nn * Nn) / 256, 256>>>(adj);
    split_x<<<dim3(BN_ROWS / 32, (INF_ / 2) / 32), dim3(32, 8)>>>(x);
    split_W<<<(H * (INF_ / 2) * (E / 4)) / 256, 256>>>(W);
    wh_gemm_mma<<<dim3(E / 128, BN_ROWS / 128, H), 256, GEMM_SMEM>>>(a1, a2);
    exp_f<<<(H * BN_ROWS) / 256, 256>>>();
    att_gemm_mma<<<dim3(E / 128, Nn / 128, H * Bb), 256, ATT_SMEM>>>();
    final_gemm<<<dim3(1, BN_ROWS / 64), 256>>>(W_act, b_act, out);
}